// round 2
// baseline (speedup 1.0000x reference)
#include <cuda_runtime.h>
#include <math.h>

#define N_NODES 100000
#define N_EDGES 3200000
#define F_IN    128
#define DIM     10
#define NB      1000
#define RS      16          // padded row stride (64B rows)
#define SCAN_BLK 512
#define SCAN_NBLK ((N_NODES + SCAN_BLK - 1) / SCAN_BLK)   // 196

// ---- scratch (__device__ globals; no allocations allowed) ----
__device__ int   d_cnt_i[N_NODES];        // in-degree per node
__device__ int   d_off[N_NODES];          // CSR row offsets (exclusive scan)
__device__ int   d_woff[N_NODES];         // working offsets for scatter
__device__ int   d_bsum[SCAN_NBLK];       // scan block sums
__device__ int   d_csr[N_EDGES];          // src indices sorted by dst
__device__ float d_p1[N_NODES * RS];      // x @ W1a
__device__ float d_q1[N_NODES * RS];      // x @ W1b
__device__ float d_p2[N_NODES * RS];      // h @ W2a
__device__ float d_q2[N_NODES * RS];      // h @ W2b
__device__ float d_pool[NB];
__device__ float d_cntB[NB];

// ---------------------------------------------------------------------------
// K0: zero counters
// ---------------------------------------------------------------------------
__global__ void k_zero() {
    int i = blockIdx.x * blockDim.x + threadIdx.x;
    if (i < N_NODES) d_cnt_i[i] = 0;
    if (i < NB) { d_pool[i] = 0.0f; d_cntB[i] = 0.0f; }
}

// ---------------------------------------------------------------------------
// K1: histogram of dst (in-degree)
// ---------------------------------------------------------------------------
__global__ void __launch_bounds__(256) k_hist(const int* __restrict__ dst) {
    int e = blockIdx.x * blockDim.x + threadIdx.x;
    if (e < N_EDGES) atomicAdd(&d_cnt_i[dst[e]], 1);
}

// ---------------------------------------------------------------------------
// Scan: 3-kernel exclusive scan of d_cnt_i -> d_off
// ---------------------------------------------------------------------------
__global__ void __launch_bounds__(SCAN_BLK) k_scan1() {
    __shared__ int sh[SCAN_BLK];
    int t = threadIdx.x;
    int i = blockIdx.x * SCAN_BLK + t;
    int v = (i < N_NODES) ? d_cnt_i[i] : 0;
    sh[t] = v;
    __syncthreads();
#pragma unroll
    for (int ofs = 1; ofs < SCAN_BLK; ofs <<= 1) {
        int add = (t >= ofs) ? sh[t - ofs] : 0;
        __syncthreads();
        sh[t] += add;
        __syncthreads();
    }
    int incl = sh[t];
    if (i < N_NODES) d_off[i] = incl - v;          // exclusive within block
    if (t == SCAN_BLK - 1) d_bsum[blockIdx.x] = incl;
}

__global__ void __launch_bounds__(256) k_scan2() {
    __shared__ int sh[256];
    int t = threadIdx.x;
    int v = (t < SCAN_NBLK) ? d_bsum[t] : 0;
    sh[t] = v;
    __syncthreads();
#pragma unroll
    for (int ofs = 1; ofs < 256; ofs <<= 1) {
        int add = (t >= ofs) ? sh[t - ofs] : 0;
        __syncthreads();
        sh[t] += add;
        __syncthreads();
    }
    if (t < SCAN_NBLK) d_bsum[t] = sh[t] - v;      // exclusive
}

__global__ void __launch_bounds__(256) k_scan3() {
    int i = blockIdx.x * blockDim.x + threadIdx.x;
    if (i < N_NODES) {
        int o = d_off[i] + d_bsum[i / SCAN_BLK];
        d_off[i] = o;
        d_woff[i] = o;
    }
}

// ---------------------------------------------------------------------------
// K2: scatter src into CSR buckets by dst
// ---------------------------------------------------------------------------
__global__ void __launch_bounds__(256) k_scatter(const int* __restrict__ src,
                                                 const int* __restrict__ dst) {
    int e = blockIdx.x * blockDim.x + threadIdx.x;
    if (e >= N_EDGES) return;
    int d = dst[e];
    int pos = atomicAdd(&d_woff[d], 1);
    d_csr[pos] = src[e];
}

// ---------------------------------------------------------------------------
// K3: layer-1 projection.  p1 = x@W1[0:128], q1 = x@W1[128:256]
// ---------------------------------------------------------------------------
__global__ void __launch_bounds__(128) k_proj1(const float* __restrict__ x,
                                               const float* __restrict__ W1) {
    __shared__ float Ws[F_IN * 20];
    __shared__ float xs[128 * 33];

    const int t = threadIdx.x;
    for (int i = t; i < F_IN * 20; i += 128) {
        int f = i / 20, o = i % 20;
        Ws[i] = (o < 10) ? W1[f * 10 + o] : W1[(F_IN + f) * 10 + (o - 10)];
    }

    const int nodeBase = blockIdx.x * 128;
    float acc[20];
#pragma unroll
    for (int o = 0; o < 20; o++) acc[o] = 0.0f;

    for (int c = 0; c < 4; c++) {
        __syncthreads();
#pragma unroll
        for (int k = 0; k < 8; k++) {
            int idx = t + k * 128;
            int row = idx >> 3;
            int c4  = idx & 7;
            float4 v = make_float4(0.f, 0.f, 0.f, 0.f);
            int node = nodeBase + row;
            if (node < N_NODES)
                v = *(const float4*)(x + (size_t)node * F_IN + c * 32 + c4 * 4);
            float* xr = &xs[row * 33 + c4 * 4];
            xr[0] = v.x; xr[1] = v.y; xr[2] = v.z; xr[3] = v.w;
        }
        __syncthreads();
#pragma unroll
        for (int f = 0; f < 32; f++) {
            float xv = xs[t * 33 + f];
            const float* wr = &Ws[(c * 32 + f) * 20];
            float4 w0 = *(const float4*)(wr + 0);
            float4 w1 = *(const float4*)(wr + 4);
            float4 w2 = *(const float4*)(wr + 8);
            float4 w3 = *(const float4*)(wr + 12);
            float4 w4 = *(const float4*)(wr + 16);
            acc[0]  += xv * w0.x; acc[1]  += xv * w0.y; acc[2]  += xv * w0.z; acc[3]  += xv * w0.w;
            acc[4]  += xv * w1.x; acc[5]  += xv * w1.y; acc[6]  += xv * w1.z; acc[7]  += xv * w1.w;
            acc[8]  += xv * w2.x; acc[9]  += xv * w2.y; acc[10] += xv * w2.z; acc[11] += xv * w2.w;
            acc[12] += xv * w3.x; acc[13] += xv * w3.y; acc[14] += xv * w3.z; acc[15] += xv * w3.w;
            acc[16] += xv * w4.x; acc[17] += xv * w4.y; acc[18] += xv * w4.z; acc[19] += xv * w4.w;
        }
    }

    const int node = nodeBase + t;
    if (node < N_NODES) {
#pragma unroll
        for (int o = 0; o < 10; o++) {
            d_p1[(size_t)node * RS + o] = acc[o];
            d_q1[(size_t)node * RS + o] = acc[10 + o];
        }
    }
}

// ---------------------------------------------------------------------------
// K4: agg1 + layer2 fused.  Warp per node:
//   sum = sum_{e in CSR[n]} q1[src_e]  (butterfly-reduced, all lanes hold it)
//   h = relu(p1 + sum/max(cnt,1));  lanes 0..19 compute h@[W2a|W2b] -> p2,q2
// ---------------------------------------------------------------------------
__global__ void __launch_bounds__(256) k_agg1(const float* __restrict__ W2) {
    __shared__ float Ws[10 * 20];   // Ws[j*20+o]
    int t = threadIdx.x;
    if (t < 200) {
        int j = t / 20, o = t % 20;
        Ws[t] = (o < 10) ? W2[j * 10 + o] : W2[(10 + j) * 10 + (o - 10)];
    }
    __syncthreads();

    int warp = (blockIdx.x * 256 + t) >> 5;
    int lane = t & 31;
    if (warp >= N_NODES) return;

    int beg = d_off[warp];
    int cnt = d_cnt_i[warp];

    float acc[10];
#pragma unroll
    for (int o = 0; o < 10; o++) acc[o] = 0.0f;

    for (int i = lane; i < cnt; i += 32) {
        int s = d_csr[beg + i];
        const float* qr = d_q1 + (size_t)s * RS;
        float4 a = *(const float4*)(qr + 0);
        float4 b = *(const float4*)(qr + 4);
        float2 c = *(const float2*)(qr + 8);
        acc[0] += a.x; acc[1] += a.y; acc[2] += a.z; acc[3] += a.w;
        acc[4] += b.x; acc[5] += b.y; acc[6] += b.z; acc[7] += b.w;
        acc[8] += c.x; acc[9] += c.y;
    }
#pragma unroll
    for (int o = 0; o < 10; o++) {
#pragma unroll
        for (int d = 16; d > 0; d >>= 1)
            acc[o] += __shfl_xor_sync(0xffffffffu, acc[o], d);
    }

    if (lane < 20) {
        float inv = 1.0f / fmaxf((float)cnt, 1.0f);
        const float* p = d_p1 + (size_t)warp * RS;
        float out = 0.0f;
#pragma unroll
        for (int j = 0; j < 10; j++) {
            float h = fmaxf(p[j] + acc[j] * inv, 0.0f);
            out += h * Ws[j * 20 + lane];
        }
        if (lane < 10) d_p2[(size_t)warp * RS + lane] = out;
        else           d_q2[(size_t)warp * RS + (lane - 10)] = out;
    }
}

// ---------------------------------------------------------------------------
// K5: agg2 + fc + pool fused.  Warp per node:
//   sum = sum q2[src];  h2 = p2 + sum/max(cnt,1);  s = h2 . Wfc
//   atomicAdd(pool[batch[n]], s); atomicAdd(cntB[batch[n]], 1)
// ---------------------------------------------------------------------------
__global__ void __launch_bounds__(256) k_agg2(const int* __restrict__ batch,
                                              const float* __restrict__ Wfc) {
    int t = threadIdx.x;
    int warp = (blockIdx.x * 256 + t) >> 5;
    int lane = t & 31;
    if (warp >= N_NODES) return;

    int beg = d_off[warp];
    int cnt = d_cnt_i[warp];

    float acc[10];
#pragma unroll
    for (int o = 0; o < 10; o++) acc[o] = 0.0f;

    for (int i = lane; i < cnt; i += 32) {
        int s = d_csr[beg + i];
        const float* qr = d_q2 + (size_t)s * RS;
        float4 a = *(const float4*)(qr + 0);
        float4 b = *(const float4*)(qr + 4);
        float2 c = *(const float2*)(qr + 8);
        acc[0] += a.x; acc[1] += a.y; acc[2] += a.z; acc[3] += a.w;
        acc[4] += b.x; acc[5] += b.y; acc[6] += b.z; acc[7] += b.w;
        acc[8] += c.x; acc[9] += c.y;
    }
#pragma unroll
    for (int o = 0; o < 10; o++) {
#pragma unroll
        for (int d = 16; d > 0; d >>= 1)
            acc[o] += __shfl_xor_sync(0xffffffffu, acc[o], d);
    }

    if (lane == 0) {
        float inv = 1.0f / fmaxf((float)cnt, 1.0f);
        const float* p = d_p2 + (size_t)warp * RS;
        float s = 0.0f;
#pragma unroll
        for (int j = 0; j < 10; j++)
            s += (p[j] + acc[j] * inv) * __ldg(&Wfc[j]);
        int b = batch[warp];
        atomicAdd(&d_pool[b], s);
        atomicAdd(&d_cntB[b], 1.0f);
    }
}

// ---------------------------------------------------------------------------
// K6: out[b] = sigmoid(pool[b] / max(cntB[b],1))
// ---------------------------------------------------------------------------
__global__ void k_out(float* __restrict__ out) {
    int b = blockIdx.x * blockDim.x + threadIdx.x;
    if (b < NB) {
        float g = d_pool[b] / fmaxf(d_cntB[b], 1.0f);
        out[b] = 1.0f / (1.0f + expf(-g));
    }
}

// ---------------------------------------------------------------------------
extern "C" void kernel_launch(void* const* d_in, const int* in_sizes, int n_in,
                              void* d_out, int out_size) {
    const float* x   = (const float*)d_in[0];
    const int*   ei  = (const int*)d_in[1];
    const int*   bat = (const int*)d_in[2];
    const float* W1  = (const float*)d_in[3];
    const float* W2  = (const float*)d_in[4];
    const float* Wfc = (const float*)d_in[5];
    float* out = (float*)d_out;

    const int* src = ei;
    const int* dst = ei + N_EDGES;

    const int AGG_BLOCKS = (N_NODES * 32 + 255) / 256;   // 12500

    k_zero<<<(N_NODES + 255) / 256, 256>>>();
    k_hist<<<(N_EDGES + 255) / 256, 256>>>(dst);
    k_scan1<<<SCAN_NBLK, SCAN_BLK>>>();
    k_scan2<<<1, 256>>>();
    k_scan3<<<(N_NODES + 255) / 256, 256>>>();
    k_scatter<<<(N_EDGES + 255) / 256, 256>>>(src, dst);
    k_proj1<<<(N_NODES + 127) / 128, 128>>>(x, W1);
    k_agg1<<<AGG_BLOCKS, 256>>>(W2);
    k_agg2<<<AGG_BLOCKS, 256>>>(bat, Wfc);
    k_out<<<(NB + 255) / 256, 256>>>(out);
}

// round 3
// speedup vs baseline: 1.3829x; 1.3829x over previous
#include <cuda_runtime.h>
#include <cuda_fp16.h>
#include <math.h>

#define N_NODES 100000
#define N_EDGES 3200000
#define F_IN    128
#define NB      1000
#define RS      16          // f32 row stride (64B)
#define QH      8           // half2 per q row (32B)

#define PROJ_B  ((N_NODES + 127) / 128)              // 782
#define DEG_B   (N_EDGES / 128)                      // 25000
#define ZERO_N  (2 * N_NODES * RS / 4)               // 800000 float4
#define ZERO_B  (ZERO_N / 128)                       // 6250
#define FUSED_B (PROJ_B + DEG_B + ZERO_B)

// ---- scratch (__device__ globals; no allocations allowed) ----
__device__ int     d_cnt[N_NODES];
__device__ float   d_p1[N_NODES * RS];
__device__ __half2 d_q1[N_NODES * QH];
__device__ float   d_ag1[N_NODES * RS];
__device__ float   d_p2[N_NODES * RS];
__device__ __half2 d_q2[N_NODES * QH];
__device__ float   d_ag2[N_NODES * RS];
__device__ float   d_pool[NB];
__device__ float   d_cntB[NB];

// ---------------------------------------------------------------------------
// K1: zero cnt   (must precede the fused kernel's deg atomics)
// ---------------------------------------------------------------------------
__global__ void k_zero_cnt() {
    int i = blockIdx.x * blockDim.x + threadIdx.x;
    if (i < N_NODES) d_cnt[i] = 0;
}

// K2: zero pool accumulators (tiny; also pads launch count for ncu targeting)
__global__ void k_zero_pool() {
    int i = threadIdx.x;
    if (i < NB) { d_pool[i] = 0.0f; d_cntB[i] = 0.0f; }
}

// ---------------------------------------------------------------------------
// K3 (fused): block ranges
//   [0, PROJ_B)                : p1 = x@W1a (f32), q1 = x@W1b (f16)
//   [PROJ_B, PROJ_B+DEG_B)     : in-degree histogram
//   [.., +ZERO_B)              : zero ag1/ag2
// ---------------------------------------------------------------------------
__global__ void __launch_bounds__(128) k_fused(const float* __restrict__ x,
                                               const float* __restrict__ W1,
                                               const int* __restrict__ dst) {
    const int b = blockIdx.x;
    const int t = threadIdx.x;

    if (b >= PROJ_B) {
        int r = b - PROJ_B;
        if (r < DEG_B) {                           // degree histogram
            int e = r * 128 + t;
            atomicAdd(&d_cnt[dst[e]], 1);
        } else {                                   // zero ag1/ag2 as float4
            int z = (r - DEG_B) * 128 + t;
            float4 zv = make_float4(0.f, 0.f, 0.f, 0.f);
            if (z < ZERO_N / 2) ((float4*)d_ag1)[z] = zv;
            else                ((float4*)d_ag2)[z - ZERO_N / 2] = zv;
        }
        return;
    }

    // ---- projection path ----
    __shared__ float Ws[F_IN * 20];     // Ws[f*20+o]: o<10 -> W1a, o>=10 -> W1b
    __shared__ float xs[128 * 33];

    for (int i = t; i < F_IN * 20; i += 128) {
        int f = i / 20, o = i % 20;
        Ws[i] = (o < 10) ? W1[f * 10 + o] : W1[(F_IN + f) * 10 + (o - 10)];
    }

    const int nodeBase = b * 128;
    float acc[20];
#pragma unroll
    for (int o = 0; o < 20; o++) acc[o] = 0.0f;

    for (int c = 0; c < 4; c++) {
        __syncthreads();
#pragma unroll
        for (int k = 0; k < 8; k++) {
            int idx = t + k * 128;
            int row = idx >> 3;
            int c4  = idx & 7;
            float4 v = make_float4(0.f, 0.f, 0.f, 0.f);
            int node = nodeBase + row;
            if (node < N_NODES)
                v = *(const float4*)(x + (size_t)node * F_IN + c * 32 + c4 * 4);
            float* xr = &xs[row * 33 + c4 * 4];
            xr[0] = v.x; xr[1] = v.y; xr[2] = v.z; xr[3] = v.w;
        }
        __syncthreads();
#pragma unroll
        for (int f = 0; f < 32; f++) {
            float xv = xs[t * 33 + f];
            const float* wr = &Ws[(c * 32 + f) * 20];
            float4 w0 = *(const float4*)(wr + 0);
            float4 w1 = *(const float4*)(wr + 4);
            float4 w2 = *(const float4*)(wr + 8);
            float4 w3 = *(const float4*)(wr + 12);
            float4 w4 = *(const float4*)(wr + 16);
            acc[0]  += xv * w0.x; acc[1]  += xv * w0.y; acc[2]  += xv * w0.z; acc[3]  += xv * w0.w;
            acc[4]  += xv * w1.x; acc[5]  += xv * w1.y; acc[6]  += xv * w1.z; acc[7]  += xv * w1.w;
            acc[8]  += xv * w2.x; acc[9]  += xv * w2.y; acc[10] += xv * w2.z; acc[11] += xv * w2.w;
            acc[12] += xv * w3.x; acc[13] += xv * w3.y; acc[14] += xv * w3.z; acc[15] += xv * w3.w;
            acc[16] += xv * w4.x; acc[17] += xv * w4.y; acc[18] += xv * w4.z; acc[19] += xv * w4.w;
        }
    }

    const int node = nodeBase + t;
    if (node < N_NODES) {
        float* pr = d_p1 + (size_t)node * RS;
        *(float4*)(pr + 0) = make_float4(acc[0], acc[1], acc[2], acc[3]);
        *(float4*)(pr + 4) = make_float4(acc[4], acc[5], acc[6], acc[7]);
        *(float2*)(pr + 8) = make_float2(acc[8], acc[9]);
        __half2 h[5];
#pragma unroll
        for (int i = 0; i < 5; i++)
            h[i] = __floats2half2_rn(acc[10 + 2 * i], acc[11 + 2 * i]);
        __half2* qr = d_q1 + (size_t)node * QH;
        uint4 u;
        u.x = *(unsigned*)&h[0]; u.y = *(unsigned*)&h[1];
        u.z = *(unsigned*)&h[2]; u.w = *(unsigned*)&h[3];
        *(uint4*)qr = u;
        qr[4] = h[4];
    }
}

// ---------------------------------------------------------------------------
// K4/K6: edge aggregation.  ag[dst] += f32(q_f16[src])  (2 LDG + 3 RED)
// ---------------------------------------------------------------------------
__device__ __forceinline__ void red4(float* p, float4 v) {
    asm volatile("red.global.add.v4.f32 [%0], {%1,%2,%3,%4};"
                 :: "l"(p), "f"(v.x), "f"(v.y), "f"(v.z), "f"(v.w) : "memory");
}
__device__ __forceinline__ void red2(float* p, float2 v) {
    asm volatile("red.global.add.v2.f32 [%0], {%1,%2};"
                 :: "l"(p), "f"(v.x), "f"(v.y) : "memory");
}

__global__ void __launch_bounds__(256) k_edge(const int* __restrict__ src,
                                              const int* __restrict__ dst,
                                              const __half2* __restrict__ q,
                                              float* __restrict__ ag) {
    int e = blockIdx.x * blockDim.x + threadIdx.x;
    if (e >= N_EDGES) return;
    int s = src[e], d = dst[e];
    const __half2* qr = q + (size_t)s * QH;
    uint4 u = *(const uint4*)qr;            // half2 0..3
    __half2 h4 = qr[4];                     // half2 4
    float2 f0 = __half22float2(*(__half2*)&u.x);
    float2 f1 = __half22float2(*(__half2*)&u.y);
    float2 f2 = __half22float2(*(__half2*)&u.z);
    float2 f3 = __half22float2(*(__half2*)&u.w);
    float2 f4 = __half22float2(h4);
    float* dr = ag + (size_t)d * RS;
    red4(dr + 0, make_float4(f0.x, f0.y, f1.x, f1.y));
    red4(dr + 4, make_float4(f2.x, f2.y, f3.x, f3.y));
    red2(dr + 8, f4);
}

// ---------------------------------------------------------------------------
// K5: h = relu(p1 + ag1/max(cnt,1));  p2 = h@W2a (f32), q2 = h@W2b (f16)
// ---------------------------------------------------------------------------
__global__ void __launch_bounds__(256) k_layer2(const float* __restrict__ W2) {
    __shared__ float Ws[10 * 20];
    int t = threadIdx.x;
    if (t < 200) {
        int j = t / 20, o = t % 20;
        Ws[t] = (o < 10) ? W2[j * 10 + o] : W2[(10 + j) * 10 + (o - 10)];
    }
    __syncthreads();

    int node = blockIdx.x * blockDim.x + t;
    if (node >= N_NODES) return;
    float inv = 1.0f / fmaxf((float)d_cnt[node], 1.0f);

    const float* p = d_p1 + (size_t)node * RS;
    const float* a = d_ag1 + (size_t)node * RS;
    float4 p0 = *(const float4*)(p + 0), p1v = *(const float4*)(p + 4);
    float2 p2v = *(const float2*)(p + 8);
    float4 a0 = *(const float4*)(a + 0), a1 = *(const float4*)(a + 4);
    float2 a2 = *(const float2*)(a + 8);

    float h[10];
    h[0] = fmaxf(p0.x + a0.x * inv, 0.f); h[1] = fmaxf(p0.y + a0.y * inv, 0.f);
    h[2] = fmaxf(p0.z + a0.z * inv, 0.f); h[3] = fmaxf(p0.w + a0.w * inv, 0.f);
    h[4] = fmaxf(p1v.x + a1.x * inv, 0.f); h[5] = fmaxf(p1v.y + a1.y * inv, 0.f);
    h[6] = fmaxf(p1v.z + a1.z * inv, 0.f); h[7] = fmaxf(p1v.w + a1.w * inv, 0.f);
    h[8] = fmaxf(p2v.x + a2.x * inv, 0.f); h[9] = fmaxf(p2v.y + a2.y * inv, 0.f);

    float acc[20];
#pragma unroll
    for (int o = 0; o < 20; o++) acc[o] = 0.0f;
#pragma unroll
    for (int j = 0; j < 10; j++) {
        float hv = h[j];
#pragma unroll
        for (int o = 0; o < 20; o++) acc[o] += hv * Ws[j * 20 + o];
    }

    float* pr = d_p2 + (size_t)node * RS;
    *(float4*)(pr + 0) = make_float4(acc[0], acc[1], acc[2], acc[3]);
    *(float4*)(pr + 4) = make_float4(acc[4], acc[5], acc[6], acc[7]);
    *(float2*)(pr + 8) = make_float2(acc[8], acc[9]);
    __half2 hh[5];
#pragma unroll
    for (int i = 0; i < 5; i++)
        hh[i] = __floats2half2_rn(acc[10 + 2 * i], acc[11 + 2 * i]);
    __half2* qr = d_q2 + (size_t)node * QH;
    uint4 u;
    u.x = *(unsigned*)&hh[0]; u.y = *(unsigned*)&hh[1];
    u.z = *(unsigned*)&hh[2]; u.w = *(unsigned*)&hh[3];
    *(uint4*)qr = u;
    qr[4] = hh[4];
}

// ---------------------------------------------------------------------------
// K7: h2 = p2 + ag2/max(cnt,1);  s = h2 . Wfc;  pool[batch] += s; cntB++
// ---------------------------------------------------------------------------
__global__ void __launch_bounds__(256) k_pool(const int* __restrict__ batch,
                                              const float* __restrict__ Wfc) {
    int node = blockIdx.x * blockDim.x + threadIdx.x;
    if (node >= N_NODES) return;
    float inv = 1.0f / fmaxf((float)d_cnt[node], 1.0f);
    const float* p = d_p2 + (size_t)node * RS;
    const float* a = d_ag2 + (size_t)node * RS;
    float4 p0 = *(const float4*)(p + 0), p1v = *(const float4*)(p + 4);
    float2 p2v = *(const float2*)(p + 8);
    float4 a0 = *(const float4*)(a + 0), a1 = *(const float4*)(a + 4);
    float2 a2 = *(const float2*)(a + 8);
    float s = 0.0f;
    s += (p0.x + a0.x * inv) * __ldg(&Wfc[0]);
    s += (p0.y + a0.y * inv) * __ldg(&Wfc[1]);
    s += (p0.z + a0.z * inv) * __ldg(&Wfc[2]);
    s += (p0.w + a0.w * inv) * __ldg(&Wfc[3]);
    s += (p1v.x + a1.x * inv) * __ldg(&Wfc[4]);
    s += (p1v.y + a1.y * inv) * __ldg(&Wfc[5]);
    s += (p1v.z + a1.z * inv) * __ldg(&Wfc[6]);
    s += (p1v.w + a1.w * inv) * __ldg(&Wfc[7]);
    s += (p2v.x + a2.x * inv) * __ldg(&Wfc[8]);
    s += (p2v.y + a2.y * inv) * __ldg(&Wfc[9]);
    int bidx = batch[node];
    atomicAdd(&d_pool[bidx], s);
    atomicAdd(&d_cntB[bidx], 1.0f);
}

// ---------------------------------------------------------------------------
// K8: out[b] = sigmoid(pool[b] / max(cntB[b],1))
// ---------------------------------------------------------------------------
__global__ void k_out(float* __restrict__ out) {
    int b = blockIdx.x * blockDim.x + threadIdx.x;
    if (b < NB) {
        float g = d_pool[b] / fmaxf(d_cntB[b], 1.0f);
        out[b] = 1.0f / (1.0f + expf(-g));
    }
}

// ---------------------------------------------------------------------------
extern "C" void kernel_launch(void* const* d_in, const int* in_sizes, int n_in,
                              void* d_out, int out_size) {
    const float* x   = (const float*)d_in[0];
    const int*   ei  = (const int*)d_in[1];
    const int*   bat = (const int*)d_in[2];
    const float* W1  = (const float*)d_in[3];
    const float* W2  = (const float*)d_in[4];
    const float* Wfc = (const float*)d_in[5];
    float* out = (float*)d_out;

    const int* src = ei;
    const int* dst = ei + N_EDGES;

    // device-symbol pointers for the edge kernel
    __half2* q1p; float* ag1p; __half2* q2p; float* ag2p;
    cudaGetSymbolAddress((void**)&q1p,  d_q1);
    cudaGetSymbolAddress((void**)&ag1p, d_ag1);
    cudaGetSymbolAddress((void**)&q2p,  d_q2);
    cudaGetSymbolAddress((void**)&ag2p, d_ag2);

    k_zero_cnt<<<(N_NODES + 255) / 256, 256>>>();                 // 1
    k_zero_pool<<<1, 1024>>>();                                   // 2
    k_fused<<<FUSED_B, 128>>>(x, W1, dst);                        // 3
    k_edge<<<(N_EDGES + 255) / 256, 256>>>(src, dst, q1p, ag1p);  // 4 (profiled)
    k_layer2<<<(N_NODES + 255) / 256, 256>>>(W2);                 // 5
    k_edge<<<(N_EDGES + 255) / 256, 256>>>(src, dst, q2p, ag2p);  // 6
    k_pool<<<(N_NODES + 255) / 256, 256>>>(bat, Wfc);             // 7
    k_out<<<(NB + 255) / 256, 256>>>(out);                        // 8
}

// round 4
// speedup vs baseline: 1.7220x; 1.2453x over previous
#include <cuda_runtime.h>
#include <cuda_fp16.h>
#include <math.h>

#define N_NODES 100000
#define N_EDGES 3200000
#define F_IN    128
#define NB      1000
#define RS      16          // f32 row stride (64B)
#define QH      8           // half2 per q row (32B)

#define PROJ_B  ((N_NODES + 127) / 128)              // 782
#define DEG_B   (N_EDGES / 128)                      // 25000
#define FUSED_B (PROJ_B + DEG_B)

// ---- scratch (__device__ globals; no allocations allowed) ----
__device__ int     d_cnt[N_NODES];
__device__ float   d_p1[N_NODES * RS];
__device__ __half2 d_q1[N_NODES * QH];
__device__ float   d_ag1[N_NODES * RS];
__device__ float   d_p2s[N_NODES];        // h . (W2a@Wfc)
__device__ float   d_r2[N_NODES];         // h . (W2b@Wfc)
__device__ float   d_ag2s[N_NODES];       // scalar neighbor sum of r2
__device__ float   d_pool[NB];
__device__ float   d_cntB[NB];

// ---------------------------------------------------------------------------
// launch 1: zero cnt
__global__ void k_zero_cnt() {
    int i = blockIdx.x * blockDim.x + threadIdx.x;
    if (i < N_NODES) d_cnt[i] = 0;
}
// launch 2: zero pool
__global__ void k_zero_pool() {
    int i = threadIdx.x;
    if (i < NB) { d_pool[i] = 0.0f; d_cntB[i] = 0.0f; }
}
// launch 4: zero ag1 (float4)
__global__ void k_zero_ag1() {
    int i = blockIdx.x * blockDim.x + threadIdx.x;
    if (i < N_NODES * RS / 4)
        ((float4*)d_ag1)[i] = make_float4(0.f, 0.f, 0.f, 0.f);
}
// launch 5: zero ag2s
__global__ void k_zero_ag2s() {
    int i = blockIdx.x * blockDim.x + threadIdx.x;
    if (i < N_NODES) d_ag2s[i] = 0.0f;
}

// ---------------------------------------------------------------------------
// launch 3 (fused): blocks [0,PROJ_B): p1 = x@W1a (f32), q1 = x@W1b (f16)
//                   blocks [PROJ_B,..): in-degree histogram
// ---------------------------------------------------------------------------
__global__ void __launch_bounds__(128) k_fused(const float* __restrict__ x,
                                               const float* __restrict__ W1,
                                               const int* __restrict__ dst) {
    const int b = blockIdx.x;
    const int t = threadIdx.x;

    if (b >= PROJ_B) {                     // degree histogram
        int e = (b - PROJ_B) * 128 + t;
        atomicAdd(&d_cnt[dst[e]], 1);
        return;
    }

    __shared__ float Ws[F_IN * 20];     // Ws[f*20+o]: o<10 -> W1a, o>=10 -> W1b
    __shared__ float xs[128 * 33];

    for (int i = t; i < F_IN * 20; i += 128) {
        int f = i / 20, o = i % 20;
        Ws[i] = (o < 10) ? W1[f * 10 + o] : W1[(F_IN + f) * 10 + (o - 10)];
    }

    const int nodeBase = b * 128;
    float acc[20];
#pragma unroll
    for (int o = 0; o < 20; o++) acc[o] = 0.0f;

    for (int c = 0; c < 4; c++) {
        __syncthreads();
#pragma unroll
        for (int k = 0; k < 8; k++) {
            int idx = t + k * 128;
            int row = idx >> 3;
            int c4  = idx & 7;
            float4 v = make_float4(0.f, 0.f, 0.f, 0.f);
            int node = nodeBase + row;
            if (node < N_NODES)
                v = *(const float4*)(x + (size_t)node * F_IN + c * 32 + c4 * 4);
            float* xr = &xs[row * 33 + c4 * 4];
            xr[0] = v.x; xr[1] = v.y; xr[2] = v.z; xr[3] = v.w;
        }
        __syncthreads();
#pragma unroll
        for (int f = 0; f < 32; f++) {
            float xv = xs[t * 33 + f];
            const float* wr = &Ws[(c * 32 + f) * 20];
            float4 w0 = *(const float4*)(wr + 0);
            float4 w1 = *(const float4*)(wr + 4);
            float4 w2 = *(const float4*)(wr + 8);
            float4 w3 = *(const float4*)(wr + 12);
            float4 w4 = *(const float4*)(wr + 16);
            acc[0]  += xv * w0.x; acc[1]  += xv * w0.y; acc[2]  += xv * w0.z; acc[3]  += xv * w0.w;
            acc[4]  += xv * w1.x; acc[5]  += xv * w1.y; acc[6]  += xv * w1.z; acc[7]  += xv * w1.w;
            acc[8]  += xv * w2.x; acc[9]  += xv * w2.y; acc[10] += xv * w2.z; acc[11] += xv * w2.w;
            acc[12] += xv * w3.x; acc[13] += xv * w3.y; acc[14] += xv * w3.z; acc[15] += xv * w3.w;
            acc[16] += xv * w4.x; acc[17] += xv * w4.y; acc[18] += xv * w4.z; acc[19] += xv * w4.w;
        }
    }

    const int node = nodeBase + t;
    if (node < N_NODES) {
        float* pr = d_p1 + (size_t)node * RS;
        *(float4*)(pr + 0) = make_float4(acc[0], acc[1], acc[2], acc[3]);
        *(float4*)(pr + 4) = make_float4(acc[4], acc[5], acc[6], acc[7]);
        *(float2*)(pr + 8) = make_float2(acc[8], acc[9]);
        __half2 h[5];
#pragma unroll
        for (int i = 0; i < 5; i++)
            h[i] = __floats2half2_rn(acc[10 + 2 * i], acc[11 + 2 * i]);
        __half2* qr = d_q1 + (size_t)node * QH;
        uint4 u;
        u.x = *(unsigned*)&h[0]; u.y = *(unsigned*)&h[1];
        u.z = *(unsigned*)&h[2]; u.w = *(unsigned*)&h[3];
        *(uint4*)qr = u;
        qr[4] = h[4];
    }
}

// ---------------------------------------------------------------------------
// launch 6 (profiled): edge pass 1.  ag1[dst] += f32(q1_f16[src])
// ---------------------------------------------------------------------------
__device__ __forceinline__ void red4(float* p, float4 v) {
    asm volatile("red.global.add.v4.f32 [%0], {%1,%2,%3,%4};"
                 :: "l"(p), "f"(v.x), "f"(v.y), "f"(v.z), "f"(v.w) : "memory");
}
__device__ __forceinline__ void red2(float* p, float2 v) {
    asm volatile("red.global.add.v2.f32 [%0], {%1,%2};"
                 :: "l"(p), "f"(v.x), "f"(v.y) : "memory");
}

__global__ void __launch_bounds__(256) k_edge1(const int* __restrict__ src,
                                               const int* __restrict__ dst) {
    int e = blockIdx.x * blockDim.x + threadIdx.x;
    if (e >= N_EDGES) return;
    int s = src[e], d = dst[e];
    const __half2* qr = d_q1 + (size_t)s * QH;
    uint4 u = *(const uint4*)qr;
    __half2 h4 = qr[4];
    float2 f0 = __half22float2(*(__half2*)&u.x);
    float2 f1 = __half22float2(*(__half2*)&u.y);
    float2 f2 = __half22float2(*(__half2*)&u.z);
    float2 f3 = __half22float2(*(__half2*)&u.w);
    float2 f4 = __half22float2(h4);
    float* dr = d_ag1 + (size_t)d * RS;
    red4(dr + 0, make_float4(f0.x, f0.y, f1.x, f1.y));
    red4(dr + 4, make_float4(f2.x, f2.y, f3.x, f3.y));
    red2(dr + 8, f4);
}

// ---------------------------------------------------------------------------
// launch 7: h = relu(p1 + ag1/max(cnt,1));  p2s = h.u, r2 = h.v
//           u = W2a@Wfc, v = W2b@Wfc  (computed per block, 20 dots of 10)
// ---------------------------------------------------------------------------
__global__ void __launch_bounds__(256) k_layer2s(const float* __restrict__ W2,
                                                 const float* __restrict__ Wfc) {
    __shared__ float uv[20];    // [0..9]=u, [10..19]=v
    int t = threadIdx.x;
    if (t < 20) {
        int j = t % 10;
        int base = (t < 10) ? j * 10 : (10 + j) * 10;
        float s = 0.0f;
#pragma unroll
        for (int o = 0; o < 10; o++) s += W2[base + o] * Wfc[o];
        uv[t] = s;
    }
    __syncthreads();

    int node = blockIdx.x * blockDim.x + t;
    if (node >= N_NODES) return;
    float inv = 1.0f / fmaxf((float)d_cnt[node], 1.0f);

    const float* p = d_p1 + (size_t)node * RS;
    const float* a = d_ag1 + (size_t)node * RS;
    float4 p0 = *(const float4*)(p + 0), p1v = *(const float4*)(p + 4);
    float2 p2v = *(const float2*)(p + 8);
    float4 a0 = *(const float4*)(a + 0), a1 = *(const float4*)(a + 4);
    float2 a2 = *(const float2*)(a + 8);

    float h[10];
    h[0] = fmaxf(p0.x + a0.x * inv, 0.f); h[1] = fmaxf(p0.y + a0.y * inv, 0.f);
    h[2] = fmaxf(p0.z + a0.z * inv, 0.f); h[3] = fmaxf(p0.w + a0.w * inv, 0.f);
    h[4] = fmaxf(p1v.x + a1.x * inv, 0.f); h[5] = fmaxf(p1v.y + a1.y * inv, 0.f);
    h[6] = fmaxf(p1v.z + a1.z * inv, 0.f); h[7] = fmaxf(p1v.w + a1.w * inv, 0.f);
    h[8] = fmaxf(p2v.x + a2.x * inv, 0.f); h[9] = fmaxf(p2v.y + a2.y * inv, 0.f);

    float ps = 0.0f, rs = 0.0f;
#pragma unroll
    for (int j = 0; j < 10; j++) {
        ps += h[j] * uv[j];
        rs += h[j] * uv[10 + j];
    }
    d_p2s[node] = ps;
    d_r2[node]  = rs;
}

// ---------------------------------------------------------------------------
// launch 8: edge pass 2 (scalar).  ag2s[dst] += r2[src]
// ---------------------------------------------------------------------------
__global__ void __launch_bounds__(256) k_edge2(const int* __restrict__ src,
                                               const int* __restrict__ dst) {
    int e = blockIdx.x * blockDim.x + threadIdx.x;
    if (e >= N_EDGES) return;
    atomicAdd(&d_ag2s[dst[e]], d_r2[src[e]]);
}

// ---------------------------------------------------------------------------
// launch 9: s = p2s + ag2s/max(cnt,1);  pool[batch] += s; cntB++
// ---------------------------------------------------------------------------
__global__ void __launch_bounds__(256) k_pool(const int* __restrict__ batch) {
    int node = blockIdx.x * blockDim.x + threadIdx.x;
    if (node >= N_NODES) return;
    float inv = 1.0f / fmaxf((float)d_cnt[node], 1.0f);
    float s = d_p2s[node] + d_ag2s[node] * inv;
    int b = batch[node];
    atomicAdd(&d_pool[b], s);
    atomicAdd(&d_cntB[b], 1.0f);
}

// ---------------------------------------------------------------------------
// launch 10: out[b] = sigmoid(pool[b] / max(cntB[b],1))
// ---------------------------------------------------------------------------
__global__ void k_out(float* __restrict__ out) {
    int b = blockIdx.x * blockDim.x + threadIdx.x;
    if (b < NB) {
        float g = d_pool[b] / fmaxf(d_cntB[b], 1.0f);
        out[b] = 1.0f / (1.0f + expf(-g));
    }
}

// ---------------------------------------------------------------------------
extern "C" void kernel_launch(void* const* d_in, const int* in_sizes, int n_in,
                              void* d_out, int out_size) {
    const float* x   = (const float*)d_in[0];
    const int*   ei  = (const int*)d_in[1];
    const int*   bat = (const int*)d_in[2];
    const float* W1  = (const float*)d_in[3];
    const float* W2  = (const float*)d_in[4];
    const float* Wfc = (const float*)d_in[5];
    float* out = (float*)d_out;

    const int* src = ei;
    const int* dst = ei + N_EDGES;

    k_zero_cnt<<<(N_NODES + 255) / 256, 256>>>();                   // 1
    k_zero_pool<<<1, 1024>>>();                                     // 2
    k_fused<<<FUSED_B, 128>>>(x, W1, dst);                          // 3
    k_zero_ag1<<<(N_NODES * RS / 4 + 255) / 256, 256>>>();          // 4
    k_zero_ag2s<<<(N_NODES + 255) / 256, 256>>>();                  // 5
    k_edge1<<<(N_EDGES + 255) / 256, 256>>>(src, dst);              // 6 (profiled)
    k_layer2s<<<(N_NODES + 255) / 256, 256>>>(W2, Wfc);             // 7
    k_edge2<<<(N_EDGES + 255) / 256, 256>>>(src, dst);              // 8
    k_pool<<<(N_NODES + 255) / 256, 256>>>(bat);                    // 9
    k_out<<<(NB + 255) / 256, 256>>>(out);                          // 10
}

// round 7
// speedup vs baseline: 1.9229x; 1.1167x over previous
#include <cuda_runtime.h>
#include <cuda_fp16.h>
#include <math.h>

#define N_NODES 100000
#define N_EDGES 3200000
#define F_IN    128
#define NB      1000
#define RS      16          // f32 row stride for p1 (64B)
#define QH      8           // half2 per q row (32B)
#define AH      8           // half2 per ag1 row (32B)

#define PROJ_B  ((N_NODES + 127) / 128)              // 782
#define DEG_B   (N_EDGES / 128)                      // 25000
#define FUSED_B (PROJ_B + DEG_B)

// ---- scratch (__device__ globals; no allocations allowed) ----
__device__ int     d_cnt[N_NODES];
__device__ float   d_p1[N_NODES * RS];
__device__ __half2 d_q1[N_NODES * QH];
__device__ __half2 d_ag1h[N_NODES * AH];  // f16 accumulators, 32B rows
__device__ float   d_p2s[N_NODES];        // h . (W2a@Wfc)
__device__ float   d_r2[N_NODES];         // h . (W2b@Wfc)
__device__ float   d_ag2s[N_NODES];       // scalar neighbor sum of r2
__device__ float   d_pool[NB];
__device__ float   d_cntB[NB];

// ---------------------------------------------------------------------------
// launch 1: zero cnt + ag1h + ag2s (float4-granular)
//   ag1h bytes = N_NODES*AH*sizeof(__half2) = 100000*8*4 = 3,200,000 B
//        -> float4 count = 3,200,000/16 = 200,000 = N_NODES*AH/4
//   ag2s: 100000 f32 = 400,000 B -> 25,000 float4
//   cnt:  100000 int = 400,000 B -> 25,000 int4
// ---------------------------------------------------------------------------
#define Z_AG1  (N_NODES * AH / 4)          // 200000 float4  (FIXED: was /2)
#define Z_AG2  (N_NODES / 4)               // 25000
#define Z_CNT  (N_NODES / 4)               // 25000
#define Z_TOT  (Z_AG1 + Z_AG2 + Z_CNT)

__global__ void __launch_bounds__(256) k_zero_main() {
    int i = blockIdx.x * blockDim.x + threadIdx.x;
    float4 z = make_float4(0.f, 0.f, 0.f, 0.f);
    if (i < Z_AG1) ((float4*)d_ag1h)[i] = z;
    else if (i < Z_AG1 + Z_AG2) ((float4*)d_ag2s)[i - Z_AG1] = z;
    else if (i < Z_TOT) ((int4*)d_cnt)[i - Z_AG1 - Z_AG2] = make_int4(0, 0, 0, 0);
}

// launch 2: zero pool
__global__ void k_zero_pool() {
    int i = threadIdx.x;
    if (i < NB) { d_pool[i] = 0.0f; d_cntB[i] = 0.0f; }
}

// ---------------------------------------------------------------------------
// launch 3 (fused): blocks [0,PROJ_B): p1 = x@W1a (f32), q1 = x@W1b (f16)
//                   blocks [PROJ_B,..): in-degree histogram
// ---------------------------------------------------------------------------
__global__ void __launch_bounds__(128) k_fused(const float* __restrict__ x,
                                               const float* __restrict__ W1,
                                               const int* __restrict__ dst) {
    const int b = blockIdx.x;
    const int t = threadIdx.x;

    if (b >= PROJ_B) {                     // degree histogram
        int e = (b - PROJ_B) * 128 + t;
        atomicAdd(&d_cnt[dst[e]], 1);
        return;
    }

    __shared__ float Ws[F_IN * 20];     // Ws[f*20+o]: o<10 -> W1a, o>=10 -> W1b
    __shared__ float xs[128 * 33];

    for (int i = t; i < F_IN * 20; i += 128) {
        int f = i / 20, o = i % 20;
        Ws[i] = (o < 10) ? W1[f * 10 + o] : W1[(F_IN + f) * 10 + (o - 10)];
    }

    const int nodeBase = b * 128;
    float acc[20];
#pragma unroll
    for (int o = 0; o < 20; o++) acc[o] = 0.0f;

    for (int c = 0; c < 4; c++) {
        __syncthreads();
#pragma unroll
        for (int k = 0; k < 8; k++) {
            int idx = t + k * 128;
            int row = idx >> 3;
            int c4  = idx & 7;
            float4 v = make_float4(0.f, 0.f, 0.f, 0.f);
            int node = nodeBase + row;
            if (node < N_NODES)
                v = *(const float4*)(x + (size_t)node * F_IN + c * 32 + c4 * 4);
            float* xr = &xs[row * 33 + c4 * 4];
            xr[0] = v.x; xr[1] = v.y; xr[2] = v.z; xr[3] = v.w;
        }
        __syncthreads();
#pragma unroll
        for (int f = 0; f < 32; f++) {
            float xv = xs[t * 33 + f];
            const float* wr = &Ws[(c * 32 + f) * 20];
            float4 w0 = *(const float4*)(wr + 0);
            float4 w1 = *(const float4*)(wr + 4);
            float4 w2 = *(const float4*)(wr + 8);
            float4 w3 = *(const float4*)(wr + 12);
            float4 w4 = *(const float4*)(wr + 16);
            acc[0]  += xv * w0.x; acc[1]  += xv * w0.y; acc[2]  += xv * w0.z; acc[3]  += xv * w0.w;
            acc[4]  += xv * w1.x; acc[5]  += xv * w1.y; acc[6]  += xv * w1.z; acc[7]  += xv * w1.w;
            acc[8]  += xv * w2.x; acc[9]  += xv * w2.y; acc[10] += xv * w2.z; acc[11] += xv * w2.w;
            acc[12] += xv * w3.x; acc[13] += xv * w3.y; acc[14] += xv * w3.z; acc[15] += xv * w3.w;
            acc[16] += xv * w4.x; acc[17] += xv * w4.y; acc[18] += xv * w4.z; acc[19] += xv * w4.w;
        }
    }

    const int node = nodeBase + t;
    if (node < N_NODES) {
        float* pr = d_p1 + (size_t)node * RS;
        *(float4*)(pr + 0) = make_float4(acc[0], acc[1], acc[2], acc[3]);
        *(float4*)(pr + 4) = make_float4(acc[4], acc[5], acc[6], acc[7]);
        *(float2*)(pr + 8) = make_float2(acc[8], acc[9]);
        __half2 h[5];
#pragma unroll
        for (int i = 0; i < 5; i++)
            h[i] = __floats2half2_rn(acc[10 + 2 * i], acc[11 + 2 * i]);
        __half2* qr = d_q1 + (size_t)node * QH;
        uint4 u;
        u.x = *(unsigned*)&h[0]; u.y = *(unsigned*)&h[1];
        u.z = *(unsigned*)&h[2]; u.w = *(unsigned*)&h[3];
        *(uint4*)qr = u;
        qr[4] = h[4];
    }
}

// ---------------------------------------------------------------------------
// launch 4 (profiled): edge pass 1.  ag1h[dst] += q1[src]  (pure f16 bits)
//   2 LDG (16B + 4B) + 2 RED (v4.f16x2 16B + f16x2 4B), zero convert math
// ---------------------------------------------------------------------------
__global__ void __launch_bounds__(256) k_edge1(const int* __restrict__ src,
                                               const int* __restrict__ dst) {
    int e = blockIdx.x * blockDim.x + threadIdx.x;
    if (e >= N_EDGES) return;
    int s = src[e], d = dst[e];
    const __half2* qr = d_q1 + (size_t)s * QH;
    uint4 u = *(const uint4*)qr;
    unsigned h4 = *(const unsigned*)(qr + 4);
    __half2* dr = d_ag1h + (size_t)d * AH;
    asm volatile("red.global.add.noftz.v4.f16x2 [%0], {%1,%2,%3,%4};"
                 :: "l"(dr), "r"(u.x), "r"(u.y), "r"(u.z), "r"(u.w) : "memory");
    asm volatile("red.global.add.noftz.f16x2 [%0], %1;"
                 :: "l"(dr + 4), "r"(h4) : "memory");
}

// ---------------------------------------------------------------------------
// launch 5: h = relu(p1 + ag1/max(cnt,1));  p2s = h.u, r2 = h.v
//           u = W2a@Wfc, v = W2b@Wfc
// ---------------------------------------------------------------------------
__global__ void __launch_bounds__(256) k_layer2s(const float* __restrict__ W2,
                                                 const float* __restrict__ Wfc) {
    __shared__ float uv[20];    // [0..9]=u, [10..19]=v
    int t = threadIdx.x;
    if (t < 20) {
        int j = t % 10;
        int base = (t < 10) ? j * 10 : (10 + j) * 10;
        float s = 0.0f;
#pragma unroll
        for (int o = 0; o < 10; o++) s += W2[base + o] * Wfc[o];
        uv[t] = s;
    }
    __syncthreads();

    int node = blockIdx.x * blockDim.x + t;
    if (node >= N_NODES) return;
    float inv = 1.0f / fmaxf((float)d_cnt[node], 1.0f);

    const float* p = d_p1 + (size_t)node * RS;
    float4 p0 = *(const float4*)(p + 0), p1v = *(const float4*)(p + 4);
    float2 p2v = *(const float2*)(p + 8);

    const __half2* ar = d_ag1h + (size_t)node * AH;
    uint4 au = *(const uint4*)ar;
    __half2 a4 = ar[4];
    float2 f0 = __half22float2(*(__half2*)&au.x);
    float2 f1 = __half22float2(*(__half2*)&au.y);
    float2 f2 = __half22float2(*(__half2*)&au.z);
    float2 f3 = __half22float2(*(__half2*)&au.w);
    float2 f4 = __half22float2(a4);

    float h[10];
    h[0] = fmaxf(p0.x + f0.x * inv, 0.f); h[1] = fmaxf(p0.y + f0.y * inv, 0.f);
    h[2] = fmaxf(p0.z + f1.x * inv, 0.f); h[3] = fmaxf(p0.w + f1.y * inv, 0.f);
    h[4] = fmaxf(p1v.x + f2.x * inv, 0.f); h[5] = fmaxf(p1v.y + f2.y * inv, 0.f);
    h[6] = fmaxf(p1v.z + f3.x * inv, 0.f); h[7] = fmaxf(p1v.w + f3.y * inv, 0.f);
    h[8] = fmaxf(p2v.x + f4.x * inv, 0.f); h[9] = fmaxf(p2v.y + f4.y * inv, 0.f);

    float ps = 0.0f, rs = 0.0f;
#pragma unroll
    for (int j = 0; j < 10; j++) {
        ps += h[j] * uv[j];
        rs += h[j] * uv[10 + j];
    }
    d_p2s[node] = ps;
    d_r2[node]  = rs;
}

// ---------------------------------------------------------------------------
// launch 6: edge pass 2 (scalar).  ag2s[dst] += r2[src]
// ---------------------------------------------------------------------------
__global__ void __launch_bounds__(256) k_edge2(const int* __restrict__ src,
                                               const int* __restrict__ dst) {
    int e = blockIdx.x * blockDim.x + threadIdx.x;
    if (e >= N_EDGES) return;
    atomicAdd(&d_ag2s[dst[e]], d_r2[src[e]]);
}

// ---------------------------------------------------------------------------
// launch 7: s = p2s + ag2s/max(cnt,1);  pool[batch] += s; cntB++
// ---------------------------------------------------------------------------
__global__ void __launch_bounds__(256) k_pool(const int* __restrict__ batch) {
    int node = blockIdx.x * blockDim.x + threadIdx.x;
    if (node >= N_NODES) return;
    float inv = 1.0f / fmaxf((float)d_cnt[node], 1.0f);
    float s = d_p2s[node] + d_ag2s[node] * inv;
    int b = batch[node];
    atomicAdd(&d_pool[b], s);
    atomicAdd(&d_cntB[b], 1.0f);
}

// ---------------------------------------------------------------------------
// launch 8: out[b] = sigmoid(pool[b] / max(cntB[b],1))
// ---------------------------------------------------------------------------
__global__ void k_out(float* __restrict__ out) {
    int b = blockIdx.x * blockDim.x + threadIdx.x;
    if (b < NB) {
        float g = d_pool[b] / fmaxf(d_cntB[b], 1.0f);
        out[b] = 1.0f / (1.0f + expf(-g));
    }
}

// ---------------------------------------------------------------------------
extern "C" void kernel_launch(void* const* d_in, const int* in_sizes, int n_in,
                              void* d_out, int out_size) {
    const float* x   = (const float*)d_in[0];
    const int*   ei  = (const int*)d_in[1];
    const int*   bat = (const int*)d_in[2];
    const float* W1  = (const float*)d_in[3];
    const float* W2  = (const float*)d_in[4];
    const float* Wfc = (const float*)d_in[5];
    float* out = (float*)d_out;

    const int* src = ei;
    const int* dst = ei + N_EDGES;

    k_zero_main<<<(Z_TOT + 255) / 256, 256>>>();                    // 1
    k_zero_pool<<<1, 1024>>>();                                     // 2
    k_fused<<<FUSED_B, 128>>>(x, W1, dst);                          // 3
    k_edge1<<<(N_EDGES + 255) / 256, 256>>>(src, dst);              // 4 (profiled)
    k_layer2s<<<(N_NODES + 255) / 256, 256>>>(W2, Wfc);             // 5
    k_edge2<<<(N_EDGES + 255) / 256, 256>>>(src, dst);              // 6
    k_pool<<<(N_NODES + 255) / 256, 256>>>(bat);                    // 7
    k_out<<<(NB + 255) / 256, 256>>>(out);                          // 8
}

// round 8
// speedup vs baseline: 2.0089x; 1.0447x over previous
#include <cuda_runtime.h>
#include <cuda_fp16.h>
#include <math.h>

#define N_NODES 100000
#define N_EDGES 3200000
#define F_IN    128
#define NB      1000
#define RS      16          // f32 row stride for p1 (64B)

#define PROJ_B  ((N_NODES + 127) / 128)              // 782

// 32-byte rows for q1 and ag1 (16 halves; [0..9]=dims, ag1[10]=count)
struct alignas(32) Row32 { uint4 a; uint4 b; };

// ---- scratch (__device__ globals; no allocations allowed) ----
__device__ Row32    d_q1[N_NODES];        // f16 projected neighbor features
__device__ Row32    d_ag1h[N_NODES];      // f16 accumulators (+count in half 10)
__device__ float    d_p1[N_NODES * RS];
__device__ float    d_p2s[N_NODES];       // h . (W2a@Wfc)
__device__ float    d_r2[N_NODES];        // h . (W2b@Wfc)
__device__ float    d_inv[N_NODES];       // 1/max(cnt,1)  (from layer2s)
__device__ float    d_ag2s[N_NODES];      // scalar neighbor sum of r2
__device__ float    d_pool[NB];
__device__ float    d_cntB[NB];
__device__ unsigned d_ticket;

// ---------------------------------------------------------------------------
// launch 1: zero ag1h + ag2s + pool + cntB + ticket  (float4-granular)
//   ag1h: 100000*32B = 3,200,000 B -> 200,000 uint4
//   ag2s: 400,000 B -> 25,000 float4
//   pool+cntB: 2*1000 f32 -> 500 float4
// ---------------------------------------------------------------------------
#define Z_AG1  (N_NODES * 2)               // 200000 uint4 (2 per Row32)
#define Z_AG2  (N_NODES / 4)               // 25000
#define Z_PB   (2 * NB / 4)                // 500
#define Z_TOT  (Z_AG1 + Z_AG2 + Z_PB)

__global__ void __launch_bounds__(256) k_zero_main() {
    int i = blockIdx.x * blockDim.x + threadIdx.x;
    uint4 z = make_uint4(0u, 0u, 0u, 0u);
    if (i < Z_AG1) ((uint4*)d_ag1h)[i] = z;
    else if (i < Z_AG1 + Z_AG2) ((uint4*)d_ag2s)[i - Z_AG1] = z;
    else if (i < Z_AG1 + Z_AG2 + Z_PB / 2) ((uint4*)d_pool)[i - Z_AG1 - Z_AG2] = z;
    else if (i < Z_TOT) ((uint4*)d_cntB)[i - Z_AG1 - Z_AG2 - Z_PB / 2] = z;
    if (i == 0) d_ticket = 0u;
}

// ---------------------------------------------------------------------------
// launch 2: projection.  p1 = x@W1a (f32), q1 = x@W1b (f16, 32B rows)
// ---------------------------------------------------------------------------
__global__ void __launch_bounds__(128) k_proj(const float* __restrict__ x,
                                              const float* __restrict__ W1) {
    __shared__ float Ws[F_IN * 20];     // Ws[f*20+o]: o<10 -> W1a, o>=10 -> W1b
    __shared__ float xs[128 * 33];

    const int t = threadIdx.x;
    for (int i = t; i < F_IN * 20; i += 128) {
        int f = i / 20, o = i % 20;
        Ws[i] = (o < 10) ? W1[f * 10 + o] : W1[(F_IN + f) * 10 + (o - 10)];
    }

    const int nodeBase = blockIdx.x * 128;
    float acc[20];
#pragma unroll
    for (int o = 0; o < 20; o++) acc[o] = 0.0f;

    for (int c = 0; c < 4; c++) {
        __syncthreads();
#pragma unroll
        for (int k = 0; k < 8; k++) {
            int idx = t + k * 128;
            int row = idx >> 3;
            int c4  = idx & 7;
            float4 v = make_float4(0.f, 0.f, 0.f, 0.f);
            int node = nodeBase + row;
            if (node < N_NODES)
                v = *(const float4*)(x + (size_t)node * F_IN + c * 32 + c4 * 4);
            float* xr = &xs[row * 33 + c4 * 4];
            xr[0] = v.x; xr[1] = v.y; xr[2] = v.z; xr[3] = v.w;
        }
        __syncthreads();
#pragma unroll
        for (int f = 0; f < 32; f++) {
            float xv = xs[t * 33 + f];
            const float* wr = &Ws[(c * 32 + f) * 20];
            float4 w0 = *(const float4*)(wr + 0);
            float4 w1 = *(const float4*)(wr + 4);
            float4 w2 = *(const float4*)(wr + 8);
            float4 w3 = *(const float4*)(wr + 12);
            float4 w4 = *(const float4*)(wr + 16);
            acc[0]  += xv * w0.x; acc[1]  += xv * w0.y; acc[2]  += xv * w0.z; acc[3]  += xv * w0.w;
            acc[4]  += xv * w1.x; acc[5]  += xv * w1.y; acc[6]  += xv * w1.z; acc[7]  += xv * w1.w;
            acc[8]  += xv * w2.x; acc[9]  += xv * w2.y; acc[10] += xv * w2.z; acc[11] += xv * w2.w;
            acc[12] += xv * w3.x; acc[13] += xv * w3.y; acc[14] += xv * w3.z; acc[15] += xv * w3.w;
            acc[16] += xv * w4.x; acc[17] += xv * w4.y; acc[18] += xv * w4.z; acc[19] += xv * w4.w;
        }
    }

    const int node = nodeBase + t;
    if (node < N_NODES) {
        float* pr = d_p1 + (size_t)node * RS;
        *(float4*)(pr + 0) = make_float4(acc[0], acc[1], acc[2], acc[3]);
        *(float4*)(pr + 4) = make_float4(acc[4], acc[5], acc[6], acc[7]);
        *(float2*)(pr + 8) = make_float2(acc[8], acc[9]);
        __half2 h[5];
#pragma unroll
        for (int i = 0; i < 5; i++)
            h[i] = __floats2half2_rn(acc[10 + 2 * i], acc[11 + 2 * i]);
        Row32* qr = &d_q1[node];
        qr->a = make_uint4(*(unsigned*)&h[0], *(unsigned*)&h[1],
                           *(unsigned*)&h[2], *(unsigned*)&h[3]);
        qr->b = make_uint4(*(unsigned*)&h[4], 0u, 0u, 0u);
    }
}

// ---------------------------------------------------------------------------
// launch 3: edge pass 1.  ag1h[dst] += {q1[src], 1.0}
//   1 LDG.256 (32B) + RED v4.f16x2 (16B) + RED v2.f16x2 (8B: dims 8,9 + count)
// ---------------------------------------------------------------------------
__global__ void __launch_bounds__(256) k_edge1(const int* __restrict__ src,
                                               const int* __restrict__ dst) {
    int e = blockIdx.x * blockDim.x + threadIdx.x;
    if (e >= N_EDGES) return;
    int s = src[e], d = dst[e];
    const Row32* qp = &d_q1[s];
    unsigned r0, r1, r2, r3, r4, r5, r6, r7;
    asm volatile("ld.global.nc.v8.b32 {%0,%1,%2,%3,%4,%5,%6,%7}, [%8];"
                 : "=r"(r0), "=r"(r1), "=r"(r2), "=r"(r3),
                   "=r"(r4), "=r"(r5), "=r"(r6), "=r"(r7)
                 : "l"(qp));
    Row32* dr = &d_ag1h[d];
    asm volatile("red.global.add.noftz.v4.f16x2 [%0], {%1,%2,%3,%4};"
                 :: "l"(dr), "r"(r0), "r"(r1), "r"(r2), "r"(r3) : "memory");
    // halves [8..11] += {d8, d9, 1.0h, 0}
    asm volatile("red.global.add.noftz.v2.f16x2 [%0], {%1,%2};"
                 :: "l"((char*)dr + 16), "r"(r4), "r"(0x00003C00u) : "memory");
}

// ---------------------------------------------------------------------------
// launch 4 (profiled): h = relu(p1 + ag1/max(cnt,1));  p2s=h.u, r2=h.v, inv
// ---------------------------------------------------------------------------
__global__ void __launch_bounds__(256) k_layer2s(const float* __restrict__ W2,
                                                 const float* __restrict__ Wfc) {
    __shared__ float uv[20];    // [0..9]=u=W2a@Wfc, [10..19]=v=W2b@Wfc
    int t = threadIdx.x;
    if (t < 20) {
        int j = t % 10;
        int base = (t < 10) ? j * 10 : (10 + j) * 10;
        float s = 0.0f;
#pragma unroll
        for (int o = 0; o < 10; o++) s += W2[base + o] * Wfc[o];
        uv[t] = s;
    }
    __syncthreads();

    int node = blockIdx.x * blockDim.x + t;
    if (node >= N_NODES) return;

    uint4 au = d_ag1h[node].a;
    uint4 bu = d_ag1h[node].b;
    float2 f0 = __half22float2(*(__half2*)&au.x);
    float2 f1 = __half22float2(*(__half2*)&au.y);
    float2 f2 = __half22float2(*(__half2*)&au.z);
    float2 f3 = __half22float2(*(__half2*)&au.w);
    float2 f4 = __half22float2(*(__half2*)&bu.x);
    float  cntf = __half2float(__low2half(*(__half2*)&bu.y));
    float inv = 1.0f / fmaxf(cntf, 1.0f);

    const float* p = d_p1 + (size_t)node * RS;
    float4 p0 = *(const float4*)(p + 0), p1v = *(const float4*)(p + 4);
    float2 p2v = *(const float2*)(p + 8);

    float h[10];
    h[0] = fmaxf(p0.x + f0.x * inv, 0.f); h[1] = fmaxf(p0.y + f0.y * inv, 0.f);
    h[2] = fmaxf(p0.z + f1.x * inv, 0.f); h[3] = fmaxf(p0.w + f1.y * inv, 0.f);
    h[4] = fmaxf(p1v.x + f2.x * inv, 0.f); h[5] = fmaxf(p1v.y + f2.y * inv, 0.f);
    h[6] = fmaxf(p1v.z + f3.x * inv, 0.f); h[7] = fmaxf(p1v.w + f3.y * inv, 0.f);
    h[8] = fmaxf(p2v.x + f4.x * inv, 0.f); h[9] = fmaxf(p2v.y + f4.y * inv, 0.f);

    float ps = 0.0f, rs = 0.0f;
#pragma unroll
    for (int j = 0; j < 10; j++) {
        ps += h[j] * uv[j];
        rs += h[j] * uv[10 + j];
    }
    d_p2s[node] = ps;
    d_r2[node]  = rs;
    d_inv[node] = inv;
}

// ---------------------------------------------------------------------------
// launch 5: edge pass 2 (scalar).  ag2s[dst] += r2[src]
// ---------------------------------------------------------------------------
__global__ void __launch_bounds__(256) k_edge2(const int* __restrict__ src,
                                               const int* __restrict__ dst) {
    int e = blockIdx.x * blockDim.x + threadIdx.x;
    if (e >= N_EDGES) return;
    atomicAdd(&d_ag2s[dst[e]], __ldg(&d_r2[src[e]]));
}

// ---------------------------------------------------------------------------
// launch 6: pool + out (last-block pattern)
//   s = p2s + ag2s*inv;  pool[batch]+=s; cntB[batch]++;
//   last block: out[b] = sigmoid(pool[b]/max(cntB[b],1))
// ---------------------------------------------------------------------------
__global__ void __launch_bounds__(256) k_pool(const int* __restrict__ batch,
                                              float* __restrict__ out) {
    int node = blockIdx.x * blockDim.x + threadIdx.x;
    if (node < N_NODES) {
        float s = d_p2s[node] + d_ag2s[node] * d_inv[node];
        int b = batch[node];
        atomicAdd(&d_pool[b], s);
        atomicAdd(&d_cntB[b], 1.0f);
    }
    __threadfence();
    __syncthreads();
    __shared__ bool last;
    if (threadIdx.x == 0) {
        unsigned tk = atomicAdd(&d_ticket, 1u);
        last = (tk == gridDim.x - 1);
    }
    __syncthreads();
    if (last) {
        __threadfence();
        for (int b = threadIdx.x; b < NB; b += blockDim.x) {
            float g = d_pool[b] / fmaxf(d_cntB[b], 1.0f);
            out[b] = 1.0f / (1.0f + expf(-g));
        }
    }
}

// ---------------------------------------------------------------------------
extern "C" void kernel_launch(void* const* d_in, const int* in_sizes, int n_in,
                              void* d_out, int out_size) {
    const float* x   = (const float*)d_in[0];
    const int*   ei  = (const int*)d_in[1];
    const int*   bat = (const int*)d_in[2];
    const float* W1  = (const float*)d_in[3];
    const float* W2  = (const float*)d_in[4];
    const float* Wfc = (const float*)d_in[5];
    float* out = (float*)d_out;

    const int* src = ei;
    const int* dst = ei + N_EDGES;

    k_zero_main<<<(Z_TOT + 255) / 256, 256>>>();                    // 1
    k_proj<<<PROJ_B, 128>>>(x, W1);                                 // 2
    k_edge1<<<(N_EDGES + 255) / 256, 256>>>(src, dst);              // 3
    k_layer2s<<<(N_NODES + 255) / 256, 256>>>(W2, Wfc);             // 4 (profiled)
    k_edge2<<<(N_EDGES + 255) / 256, 256>>>(src, dst);              // 5
    k_pool<<<(N_NODES + 255) / 256, 256>>>(bat, out);               // 6
}